// round 9
// baseline (speedup 1.0000x reference)
#include <cuda_runtime.h>
#include <cstdint>

#define BH   64
#define S    2048
#define RNK  64
#define D    64
#define NELEM (BH*S*RNK)
#define NSPLIT 8

#define JAX_PARTITIONABLE 1

__device__ __align__(16) float g_L   [NELEM];
__device__ __align__(16) float g_Rp  [NELEM];
__device__ __align__(16) float g_ls  [NELEM];
__device__ __align__(16) float g_rs  [NELEM];
__device__ __align__(16) float g_dtmp[NELEM];
__device__ __align__(16) float g_part[5*BH*NSPLIT*4096];
__device__ float g_invL[BH*S];
__device__ float g_invR[BH*RNK];
__device__ float g_pdot[BH*RNK*32];
__device__ float g_G [BH*RNK*RNK];
__device__ float g_H [BH*RNK*RNK];
__device__ float g_P [BH*RNK*D];
__device__ float g_RK[BH*RNK*D];
__device__ float g_W [BH*RNK*D];

__host__ __device__ inline uint32_t rotl_(uint32_t x, int r) {
#ifdef __CUDA_ARCH__
    return __funnelshift_l(x, x, r);
#else
    return (x << r) | (x >> (32 - r));
#endif
}

__host__ __device__ inline void tf2x32(uint32_t k0, uint32_t k1,
                                       uint32_t x0, uint32_t x1,
                                       uint32_t* o0, uint32_t* o1) {
    uint32_t ks0 = k0, ks1 = k1, ks2 = k0 ^ k1 ^ 0x1BD11BDAu;
    x0 += ks0; x1 += ks1;
#define TF_RND(r) { x0 += x1; x1 = rotl_(x1, r); x1 ^= x0; }
    TF_RND(13) TF_RND(15) TF_RND(26) TF_RND(6)
    x0 += ks1; x1 += ks2 + 1u;
    TF_RND(17) TF_RND(29) TF_RND(16) TF_RND(24)
    x0 += ks2; x1 += ks0 + 2u;
    TF_RND(13) TF_RND(15) TF_RND(26) TF_RND(6)
    x0 += ks0; x1 += ks1 + 3u;
    TF_RND(17) TF_RND(29) TF_RND(16) TF_RND(24)
    x0 += ks1; x1 += ks2 + 4u;
    TF_RND(13) TF_RND(15) TF_RND(26) TF_RND(6)
    x0 += ks2; x1 += ks0 + 5u;
#undef TF_RND
    *o0 = x0; *o1 = x1;
}

__device__ inline float bits_to_unit(uint32_t bits) {
    return __uint_as_float((bits >> 9) | 0x3F800000u) - 1.0f;
}

__device__ inline uint32_t rbits(uint32_t ka, uint32_t kb, uint32_t idx) {
    uint32_t o0, o1;
#if JAX_PARTITIONABLE
    tf2x32(ka, kb, 0u, idx, &o0, &o1);
    return o0 ^ o1;
#else
    const uint32_t HN = NELEM / 2;
    if (idx < HN) { tf2x32(ka, kb, idx, idx + HN, &o0, &o1); return o0; }
    tf2x32(ka, kb, idx - HN, idx, &o0, &o1); return o1;
#endif
}

__global__ void k_init(uint32_t la, uint32_t lb, uint32_t ra, uint32_t rb) {
    int idx = blockIdx.x * blockDim.x + threadIdx.x;
    if (idx >= NELEM) return;
    float u = bits_to_unit(rbits(la, lb, (uint32_t)idx));
    g_L[idx] = 0.125f + (0.002f * u - 0.001f);
    u = bits_to_unit(rbits(ra, rb, (uint32_t)idx));
    g_Rp[idx] = 0.022097086912079608f + (0.002f * u - 0.001f);
}

// fused prep: y<256 -> L rows (len 64); y>=256 -> R rows (len 2048). grid(64,320) x 256
__global__ void k_prep() {
    int bh = blockIdx.x;
    if (blockIdx.y < 256) {
        int w = threadIdx.x >> 5, lane = threadIdx.x & 31;
        int i = blockIdx.y * 8 + w;
        int base = bh * S * RNK + i * RNK;
        float v0 = g_L[base + lane], v1 = g_L[base + 32 + lane];
        float ss = v0 * v0 + v1 * v1;
        #pragma unroll
        for (int o = 16; o > 0; o >>= 1) ss += __shfl_xor_sync(0xffffffffu, ss, o);
        float n = sqrtf(ss);
        float inv = (n > 0.f) ? (1.0f / n) : 0.0f;
        g_ls[base + lane]      = (n > 0.f) ? v0 * inv : v0;
        g_ls[base + 32 + lane] = (n > 0.f) ? v1 * inv : v1;
        if (lane == 0) g_invL[bh * S + i] = inv;
    } else {
        int j = blockIdx.y - 256;
        int base = bh * RNK * S + j * S;
        int tid = threadIdx.x;
        float v[8]; float ss = 0.f;
        #pragma unroll
        for (int p = 0; p < 8; p++) { v[p] = g_Rp[base + p * 256 + tid]; ss += v[p] * v[p]; }
        #pragma unroll
        for (int o = 16; o > 0; o >>= 1) ss += __shfl_xor_sync(0xffffffffu, ss, o);
        __shared__ float red[8];
        if ((tid & 31) == 0) red[tid >> 5] = ss;
        __syncthreads();
        float n = sqrtf(red[0]+red[1]+red[2]+red[3]+red[4]+red[5]+red[6]+red[7]);
        float inv = (n > 0.f) ? (1.0f / n) : 0.0f;
        #pragma unroll
        for (int p = 0; p < 8; p++)
            g_rs[base + p * 256 + tid] = (n > 0.f) ? v[p] * inv : v[p];
        if (tid == 0) g_invR[bh * RNK + j] = inv;
    }
}

// split-K 64x64 contractions. mode 0:H 1:P 2:G 3:RK 4:W. grid(64,nmodes,8) x 256
__global__ void __launch_bounds__(256, 3)
k_gemm64(const float* __restrict__ q, const float* __restrict__ kin,
         const float* __restrict__ vin, int modebase) {
    __shared__ __align__(16) float Abuf[32 * 68];
    __shared__ __align__(16) float Bbuf[32 * 68];
    int bh = blockIdx.x, mode = modebase + blockIdx.y, ks = blockIdx.z;
    int tid = threadIdx.x;
    int ty = tid >> 4, tx = tid & 15;
    int kbeg = ks * (S / NSPLIT);
    float acc[4][4];
    #pragma unroll
    for (int a = 0; a < 4; a++) { acc[a][0]=0.f; acc[a][1]=0.f; acc[a][2]=0.f; acc[a][3]=0.f; }

    if (mode <= 1) {
        const float* lsb = g_ls + bh * S * RNK;
        const float* qb  = q + bh * S * D;
        for (int k0 = kbeg; k0 < kbeg + S / NSPLIT; k0 += 32) {
            #pragma unroll
            for (int p = 0; p < 8; p++) {
                int e = p * 256 + tid, r0 = e >> 6, c = e & 63;
                float x = lsb[(k0 + r0) * RNK + c];
                Abuf[r0 * 68 + c] = x * x;
                if (mode == 1) Bbuf[r0 * 68 + c] = 0.125f * qb[(k0 + r0) * D + c];
            }
            __syncthreads();
            const float* Bp = (mode == 0) ? Abuf : Bbuf;
            #pragma unroll 8
            for (int i = 0; i < 32; i++) {
                float4 av = *reinterpret_cast<const float4*>(&Abuf[i * 68 + ty * 4]);
                float4 bv = *reinterpret_cast<const float4*>(&Bp  [i * 68 + tx * 4]);
                const float* a4 = &av.x; const float* b4 = &bv.x;
                #pragma unroll
                for (int a = 0; a < 4; a++)
                    #pragma unroll
                    for (int b = 0; b < 4; b++) acc[a][b] += a4[a] * b4[b];
            }
            __syncthreads();
        }
    } else {
        const float* rsb = g_rs + bh * RNK * S;
        const float* src = (mode == 3) ? (kin + bh * S * D) : (vin + bh * S * D);
        for (int t0 = kbeg; t0 < kbeg + S / NSPLIT; t0 += 32) {
            #pragma unroll
            for (int p = 0; p < 8; p++) {
                int e = p * 256 + tid, m = e >> 5, tt = e & 31;
                float x = rsb[m * S + t0 + tt];
                Abuf[tt * 68 + m] = x * x;   // transposed store [t][m]
            }
            if (mode >= 3) {
                #pragma unroll
                for (int p = 0; p < 8; p++) {
                    int e = p * 256 + tid, r0 = e >> 6, c = e & 63;
                    Bbuf[r0 * 68 + c] = src[(t0 + r0) * D + c];
                }
            }
            __syncthreads();
            const float* Bp = (mode == 2) ? Abuf : Bbuf;
            #pragma unroll 8
            for (int tt = 0; tt < 32; tt++) {
                float4 av = *reinterpret_cast<const float4*>(&Abuf[tt * 68 + ty * 4]);
                float4 bv = *reinterpret_cast<const float4*>(&Bp  [tt * 68 + tx * 4]);
                const float* a4 = &av.x; const float* b4 = &bv.x;
                #pragma unroll
                for (int a = 0; a < 4; a++)
                    #pragma unroll
                    for (int b = 0; b < 4; b++) acc[a][b] += a4[a] * b4[b];
            }
            __syncthreads();
        }
    }
    float* out = g_part + (((size_t)mode * BH + bh) * NSPLIT + ks) * 4096;
    #pragma unroll
    for (int a = 0; a < 4; a++)
        #pragma unroll
        for (int b = 0; b < 4; b++)
            out[(ty * 4 + a) * 64 + tx * 4 + b] = acc[a][b];
}

// fixed-order reduce of split-K partials
__global__ void k_gred(int modebase) {
    int gid = blockIdx.x * blockDim.x + threadIdx.x;
    int e = gid & 4095;
    int bh = (gid >> 12) & 63;
    int mode = modebase + (gid >> 18);
    const float* p = g_part + (((size_t)mode * BH + bh) * NSPLIT) * 4096 + e;
    float s = 0.f;
    #pragma unroll
    for (int t = 0; t < NSPLIT; t++) s += p[t * 4096];
    float* dst;
    switch (mode) { case 0: dst = g_H; break; case 1: dst = g_P; break;
                    case 2: dst = g_G; break; case 3: dst = g_RK; break;
                    default: dst = g_W; break; }
    dst[bh * 4096 + e] = s;
}

// d_left = lsq@G - (q/8)@RK^T ; PGD row update. grid(64,16) x 256
__global__ void k_updateL(const float* __restrict__ q) {
    __shared__ float Gs [64 * 65];
    __shared__ float RKs[64 * 65];
    int bh = blockIdx.x;
    for (int e = threadIdx.x; e < 4096; e += 256) {
        int r0 = e >> 6, c = e & 63;
        Gs [r0 * 65 + c] = g_G [bh * 4096 + e];
        RKs[r0 * 65 + c] = g_RK[bh * 4096 + e];
    }
    __syncthreads();
    int w = threadIdx.x >> 5, lane = threadIdx.x & 31;
    for (int g = 0; g < 4; g++) {
        int i0 = blockIdx.y * 128 + w * 16 + g * 4;
        float ls0[4], ls1[4], lq0[4], lq1[4], qv0[4], qv1[4], a0[4], a1[4], b0[4], b1[4];
        #pragma unroll
        for (int r = 0; r < 4; r++) {
            int base = bh * S * RNK + (i0 + r) * RNK;
            ls0[r] = g_ls[base + lane]; ls1[r] = g_ls[base + 32 + lane];
            lq0[r] = ls0[r] * ls0[r];   lq1[r] = ls1[r] * ls1[r];
            qv0[r] = 0.125f * q[bh * S * D + (i0 + r) * D + lane];
            qv1[r] = 0.125f * q[bh * S * D + (i0 + r) * D + 32 + lane];
            a0[r] = 0.f; a1[r] = 0.f; b0[r] = 0.f; b1[r] = 0.f;
        }
        #pragma unroll 4
        for (int m = 0; m < 64; m++) {
            float x0 = Gs[m * 65 + lane], x1 = Gs[m * 65 + 32 + lane];
            #pragma unroll
            for (int r = 0; r < 4; r++) {
                float lv = (m < 32) ? __shfl_sync(0xffffffffu, lq0[r], m)
                                    : __shfl_sync(0xffffffffu, lq1[r], m - 32);
                a0[r] += lv * x0; a1[r] += lv * x1;
            }
        }
        #pragma unroll 4
        for (int d = 0; d < 64; d++) {
            float y0 = RKs[lane * 65 + d], y1 = RKs[(lane + 32) * 65 + d];
            #pragma unroll
            for (int r = 0; r < 4; r++) {
                float qq = (d < 32) ? __shfl_sync(0xffffffffu, qv0[r], d)
                                    : __shfl_sync(0xffffffffu, qv1[r], d - 32);
                b0[r] += qq * y0; b1[r] += qq * y1;
            }
        }
        #pragma unroll
        for (int r = 0; r < 4; r++) {
            int i = i0 + r, base = bh * S * RNK + i * RNK;
            float dl0 = (a0[r] - b0[r]) * 2.0f * ls0[r];
            float dl1 = (a1[r] - b1[r]) * 2.0f * ls1[r];
            float c = ls0[r] * dl0 + ls1[r] * dl1;
            #pragma unroll
            for (int o = 16; o > 0; o >>= 1) c += __shfl_xor_sync(0xffffffffu, c, o);
            float inv = g_invL[bh * S + i];
            g_L[base + lane]      -= inv * (dl0 - ls0[r] * c);
            g_L[base + 32 + lane] -= inv * (dl1 - ls1[r] * c);
        }
    }
}

// dtmp = 2*rs*(H@rsq - P@kT) + per-tile partial row dots. grid(64,32) x 256
__global__ void k_updateRa(const float* __restrict__ kin) {
    __shared__ float rq[64 * 65];
    __shared__ float ks[64 * 65];
    int bh = blockIdx.x, t0 = blockIdx.y * 64;
    const float* rsb = g_rs + bh * RNK * S;
    for (int e = threadIdx.x; e < 4096; e += 256) {
        int r0 = e >> 6, c = e & 63;
        float x = rsb[r0 * S + t0 + c];
        rq[r0 * 65 + c] = x * x;
        ks[r0 * 65 + c] = kin[bh * S * D + (t0 + r0) * D + c];
    }
    __syncthreads();
    int w = threadIdx.x >> 5, lane = threadIdx.x & 31;
    for (int g = 0; g < 2; g++) {
        int jb = w * 8 + g * 4;
        float h0[4], h1[4], p0[4], p1[4], a0[4], a1[4];
        #pragma unroll
        for (int r = 0; r < 4; r++) {
            int j = jb + r;
            h0[r] = g_H[bh * 4096 + j * 64 + lane];
            h1[r] = g_H[bh * 4096 + j * 64 + 32 + lane];
            p0[r] = g_P[bh * 4096 + j * 64 + lane];
            p1[r] = g_P[bh * 4096 + j * 64 + 32 + lane];
            a0[r] = 0.f; a1[r] = 0.f;
        }
        #pragma unroll 4
        for (int m = 0; m < 64; m++) {
            float x0 = rq[m * 65 + lane], x1 = rq[m * 65 + 32 + lane];
            #pragma unroll
            for (int r = 0; r < 4; r++) {
                float hv = (m < 32) ? __shfl_sync(0xffffffffu, h0[r], m)
                                    : __shfl_sync(0xffffffffu, h1[r], m - 32);
                a0[r] += hv * x0; a1[r] += hv * x1;
            }
        }
        #pragma unroll 4
        for (int d = 0; d < 64; d++) {
            float y0 = ks[lane * 65 + d], y1 = ks[(lane + 32) * 65 + d];
            #pragma unroll
            for (int r = 0; r < 4; r++) {
                float pv = (d < 32) ? __shfl_sync(0xffffffffu, p0[r], d)
                                    : __shfl_sync(0xffffffffu, p1[r], d - 32);
                a0[r] -= pv * y0; a1[r] -= pv * y1;
            }
        }
        #pragma unroll
        for (int r = 0; r < 4; r++) {
            int j = jb + r, rbase = bh * RNK * S + j * S + t0;
            float rs0 = g_rs[rbase + lane], rs1 = g_rs[rbase + 32 + lane];
            float dt0 = a0[r] * 2.0f * rs0, dt1 = a1[r] * 2.0f * rs1;
            g_dtmp[rbase + lane] = dt0;
            g_dtmp[rbase + 32 + lane] = dt1;
            float pd = rs0 * dt0 + rs1 * dt1;
            #pragma unroll
            for (int o = 16; o > 0; o >>= 1) pd += __shfl_xor_sync(0xffffffffu, pd, o);
            if (lane == 0) g_pdot[(bh * RNK + j) * 32 + blockIdx.y] = pd;
        }
    }
}

// fused rowdot + R update. grid(BH*RNK) x 256
__global__ void k_updateRb() {
    int row = blockIdx.x;
    __shared__ float srd;
    if (threadIdx.x < 32) {
        float pd = g_pdot[row * 32 + threadIdx.x];
        #pragma unroll
        for (int o = 16; o > 0; o >>= 1) pd += __shfl_xor_sync(0xffffffffu, pd, o);
        if (threadIdx.x == 0) srd = pd;
    }
    __syncthreads();
    float rd = srd, inv = g_invR[row];
    int b4 = row * (S / 4);
    #pragma unroll
    for (int p = 0; p < 2; p++) {
        int idx = b4 + p * 256 + threadIdx.x;
        float4 dt = ((const float4*)g_dtmp)[idx];
        float4 rs = ((const float4*)g_rs)[idx];
        float4 Rv = ((float4*)g_Rp)[idx];
        Rv.x -= inv * (dt.x - rs.x * rd);
        Rv.y -= inv * (dt.y - rs.y * rd);
        Rv.z -= inv * (dt.z - rs.z * rd);
        Rv.w -= inv * (dt.w - rs.w * rd);
        ((float4*)g_Rp)[idx] = Rv;
    }
}

// out = lsq^2 @ W. grid(64,16) x 256
__global__ void k_out(float* __restrict__ out) {
    __shared__ float Ws[64 * 65];
    int bh = blockIdx.x;
    for (int e = threadIdx.x; e < 4096; e += 256)
        Ws[(e >> 6) * 65 + (e & 63)] = g_W[bh * 4096 + e];
    __syncthreads();
    int w = threadIdx.x >> 5, lane = threadIdx.x & 31;
    for (int g = 0; g < 4; g++) {
        int i0 = blockIdx.y * 128 + w * 16 + g * 4;
        float lq0[4], lq1[4], o0[4], o1[4];
        #pragma unroll
        for (int r = 0; r < 4; r++) {
            int base = bh * S * RNK + (i0 + r) * RNK;
            float a = g_ls[base + lane], b = g_ls[base + 32 + lane];
            lq0[r] = a * a; lq1[r] = b * b;
            o0[r] = 0.f; o1[r] = 0.f;
        }
        #pragma unroll 4
        for (int j = 0; j < 64; j++) {
            float x0 = Ws[j * 65 + lane], x1 = Ws[j * 65 + 32 + lane];
            #pragma unroll
            for (int r = 0; r < 4; r++) {
                float lv = (j < 32) ? __shfl_sync(0xffffffffu, lq0[r], j)
                                    : __shfl_sync(0xffffffffu, lq1[r], j - 32);
                o0[r] += lv * x0; o1[r] += lv * x1;
            }
        }
        #pragma unroll
        for (int r = 0; r < 4; r++) {
            int ob = bh * S * D + (i0 + r) * D;
            out[ob + lane]      = o0[r];
            out[ob + 32 + lane] = o1[r];
        }
    }
}

extern "C" void kernel_launch(void* const* d_in, const int* in_sizes, int n_in,
                              void* d_out, int out_size) {
    const float* q = (const float*)d_in[0];
    const float* k = (const float*)d_in[1];
    const float* v = (const float*)d_in[2];
    float* out = (float*)d_out;

    uint32_t k1a, k1b, k2a, k2b;
#if JAX_PARTITIONABLE
    tf2x32(0u, 42u, 0u, 0u, &k1a, &k1b);
    tf2x32(0u, 42u, 0u, 1u, &k2a, &k2b);
#else
    { uint32_t a0, b0, a1, b1;
      tf2x32(0u, 42u, 0u, 2u, &a0, &b0);
      tf2x32(0u, 42u, 1u, 3u, &a1, &b1);
      k1a = a0; k1b = a1; k2a = b0; k2b = b1; }
#endif

    k_init<<<NELEM / 256, 256>>>(k1a, k1b, k2a, k2b);
    for (int step = 0; step < 8; step++) {
        k_prep<<<dim3(BH, 320), 256>>>();
        k_gemm64<<<dim3(BH, 4, NSPLIT), 256>>>(q, k, v, 0);   // H, P, G, RK partials
        k_gred<<<4 * BH * 4096 / 256, 256>>>(0);
        k_updateL<<<dim3(BH, 16), 256>>>(q);
        k_updateRa<<<dim3(BH, 32), 256>>>(k);
        k_updateRb<<<BH * RNK, 256>>>();
    }
    k_prep<<<dim3(BH, 320), 256>>>();
    k_gemm64<<<dim3(BH, 1, NSPLIT), 256>>>(q, k, v, 4);       // W partials
    k_gred<<<BH * 4096 / 256, 256>>>(4);
    k_out<<<dim3(BH, 16), 256>>>(out);
}

// round 10
// speedup vs baseline: 1.3564x; 1.3564x over previous
#include <cuda_runtime.h>
#include <cstdint>

#define BH   64
#define S    2048
#define RNK  64
#define D    64
#define NELEM (BH*S*RNK)
#define NSPLIT 4

#define JAX_PARTITIONABLE 1

__device__ __align__(16) float g_Rp  [NELEM];
__device__ __align__(16) float g_ls  [NELEM];
__device__ __align__(16) float g_rs  [NELEM];
__device__ __align__(16) float g_part[5*BH*NSPLIT*4096];
__device__ float g_invL[BH*S];
__device__ float g_invR[BH*RNK];
__device__ float g_rowdot[BH*RNK];
__device__ float g_G [BH*RNK*RNK];
__device__ float g_H [BH*RNK*RNK];
__device__ float g_P [BH*RNK*D];
__device__ float g_RK[BH*RNK*D];
__device__ float g_W [BH*RNK*D];

__host__ __device__ inline uint32_t rotl_(uint32_t x, int r) {
#ifdef __CUDA_ARCH__
    return __funnelshift_l(x, x, r);
#else
    return (x << r) | (x >> (32 - r));
#endif
}

__host__ __device__ inline void tf2x32(uint32_t k0, uint32_t k1,
                                       uint32_t x0, uint32_t x1,
                                       uint32_t* o0, uint32_t* o1) {
    uint32_t ks0 = k0, ks1 = k1, ks2 = k0 ^ k1 ^ 0x1BD11BDAu;
    x0 += ks0; x1 += ks1;
#define TF_RND(r) { x0 += x1; x1 = rotl_(x1, r); x1 ^= x0; }
    TF_RND(13) TF_RND(15) TF_RND(26) TF_RND(6)
    x0 += ks1; x1 += ks2 + 1u;
    TF_RND(17) TF_RND(29) TF_RND(16) TF_RND(24)
    x0 += ks2; x1 += ks0 + 2u;
    TF_RND(13) TF_RND(15) TF_RND(26) TF_RND(6)
    x0 += ks0; x1 += ks1 + 3u;
    TF_RND(17) TF_RND(29) TF_RND(16) TF_RND(24)
    x0 += ks1; x1 += ks2 + 4u;
    TF_RND(13) TF_RND(15) TF_RND(26) TF_RND(6)
    x0 += ks2; x1 += ks0 + 5u;
#undef TF_RND
    *o0 = x0; *o1 = x1;
}

__device__ inline float bits_to_unit(uint32_t bits) {
    return __uint_as_float((bits >> 9) | 0x3F800000u) - 1.0f;
}

__device__ inline uint32_t rbits(uint32_t ka, uint32_t kb, uint32_t idx) {
    uint32_t o0, o1;
#if JAX_PARTITIONABLE
    tf2x32(ka, kb, 0u, idx, &o0, &o1);
    return o0 ^ o1;
#else
    const uint32_t HN = NELEM / 2;
    if (idx < HN) { tf2x32(ka, kb, idx, idx + HN, &o0, &o1); return o0; }
    tf2x32(ka, kb, idx - HN, idx, &o0, &o1); return o1;
#endif
}

// init L: generate params per warp-row (len 64), normalize in-warp, write ls + invL.
__global__ void k_initL(uint32_t la, uint32_t lb) {
    int row = blockIdx.x * 8 + (threadIdx.x >> 5);   // 0..BH*S-1
    int lane = threadIdx.x & 31;
    int base = row * RNK;
    float u0 = bits_to_unit(rbits(la, lb, (uint32_t)(base + lane)));
    float u1 = bits_to_unit(rbits(la, lb, (uint32_t)(base + 32 + lane)));
    float v0 = 0.125f + (0.002f * u0 - 0.001f);
    float v1 = 0.125f + (0.002f * u1 - 0.001f);
    float ss = v0 * v0 + v1 * v1;
    #pragma unroll
    for (int o = 16; o > 0; o >>= 1) ss += __shfl_xor_sync(0xffffffffu, ss, o);
    float n = sqrtf(ss);
    float inv = (n > 0.f) ? (1.0f / n) : 0.0f;
    g_ls[base + lane]      = (n > 0.f) ? v0 / n : v0;
    g_ls[base + 32 + lane] = (n > 0.f) ? v1 / n : v1;
    if (lane == 0) g_invL[row] = inv;
}

// init R params elementwise (4 per thread, float4 store)
__global__ void k_initR(uint32_t ra, uint32_t rb) {
    int g4 = blockIdx.x * blockDim.x + threadIdx.x;
    int e = g4 * 4;
    float4 o;
    o.x = 0.022097086912079608f + (0.002f * bits_to_unit(rbits(ra, rb, e))     - 0.001f);
    o.y = 0.022097086912079608f + (0.002f * bits_to_unit(rbits(ra, rb, e + 1)) - 0.001f);
    o.z = 0.022097086912079608f + (0.002f * bits_to_unit(rbits(ra, rb, e + 2)) - 0.001f);
    o.w = 0.022097086912079608f + (0.002f * bits_to_unit(rbits(ra, rb, e + 3)) - 0.001f);
    ((float4*)g_Rp)[g4] = o;
}

// per-row (len 2048) sphere + inv norm of R. grid(64,64) x 256
__global__ void k_prepR() {
    int bh = blockIdx.x, j = blockIdx.y;
    int base = bh * RNK * S + j * S;
    int tid = threadIdx.x;
    float v[8]; float ss = 0.f;
    #pragma unroll
    for (int p = 0; p < 8; p++) { v[p] = g_Rp[base + p * 256 + tid]; ss += v[p] * v[p]; }
    #pragma unroll
    for (int o = 16; o > 0; o >>= 1) ss += __shfl_xor_sync(0xffffffffu, ss, o);
    __shared__ float red[8];
    if ((tid & 31) == 0) red[tid >> 5] = ss;
    __syncthreads();
    float n = sqrtf(red[0]+red[1]+red[2]+red[3]+red[4]+red[5]+red[6]+red[7]);
    float inv = (n > 0.f) ? (1.0f / n) : 0.0f;
    #pragma unroll
    for (int p = 0; p < 8; p++)
        g_rs[base + p * 256 + tid] = (n > 0.f) ? v[p] / n : v[p];
    if (tid == 0) g_invR[bh * RNK + j] = inv;
}

// split-K 64x64 contractions (R7-proven inner body). mode 0:H 1:P 2:G 3:RK 4:W.
// grid(64, nmodes, NSPLIT) x 256
__global__ void k_gemm64(const float* __restrict__ q, const float* __restrict__ kin,
                         const float* __restrict__ vin, int modebase) {
    __shared__ float Abuf[64 * 33];   // reused as [32][65]
    __shared__ float Bbuf[32 * 65];
    int bh = blockIdx.x, mode = modebase + blockIdx.y, tid = threadIdx.x;
    int ty = tid >> 4, tx = tid & 15;
    int kbeg = blockIdx.z * (S / NSPLIT);
    float acc[4][4];
    #pragma unroll
    for (int a = 0; a < 4; a++) { acc[a][0]=0.f; acc[a][1]=0.f; acc[a][2]=0.f; acc[a][3]=0.f; }

    if (mode <= 1) {
        const float* lsb = g_ls + bh * S * RNK;
        const float* qb  = q + bh * S * D;
        for (int k0 = kbeg; k0 < kbeg + S / NSPLIT; k0 += 32) {
            #pragma unroll
            for (int p = 0; p < 8; p++) {
                int e = p * 256 + tid, r0 = e >> 6, c = e & 63;
                float x = lsb[(k0 + r0) * RNK + c];
                Abuf[r0 * 65 + c] = x * x;
                if (mode == 1) Bbuf[r0 * 65 + c] = 0.125f * qb[(k0 + r0) * D + c];
            }
            __syncthreads();
            const float* Bp = (mode == 0) ? Abuf : Bbuf;
            #pragma unroll 4
            for (int i = 0; i < 32; i++) {
                float av[4], bv[4];
                #pragma unroll
                for (int a = 0; a < 4; a++) av[a] = Abuf[i * 65 + ty * 4 + a];
                #pragma unroll
                for (int b = 0; b < 4; b++) bv[b] = Bp[i * 65 + tx * 4 + b];
                #pragma unroll
                for (int a = 0; a < 4; a++)
                    #pragma unroll
                    for (int b = 0; b < 4; b++) acc[a][b] += av[a] * bv[b];
            }
            __syncthreads();
        }
    } else {
        const float* rsb = g_rs + bh * RNK * S;
        const float* src = (mode == 3) ? (kin + bh * S * D) : (vin + bh * S * D);
        for (int t0 = kbeg; t0 < kbeg + S / NSPLIT; t0 += 32) {
            #pragma unroll
            for (int p = 0; p < 8; p++) {
                int e = p * 256 + tid, m = e >> 5, tt = e & 31;
                float x = rsb[m * S + t0 + tt];
                Abuf[m * 33 + tt] = x * x;
            }
            if (mode >= 3) {
                #pragma unroll
                for (int p = 0; p < 8; p++) {
                    int e = p * 256 + tid, r0 = e >> 6, c = e & 63;
                    Bbuf[r0 * 65 + c] = src[(t0 + r0) * D + c];
                }
            }
            __syncthreads();
            #pragma unroll 4
            for (int tt = 0; tt < 32; tt++) {
                float av[4], bv[4];
                #pragma unroll
                for (int a = 0; a < 4; a++) av[a] = Abuf[(ty * 4 + a) * 33 + tt];
                if (mode == 2) {
                    #pragma unroll
                    for (int b = 0; b < 4; b++) bv[b] = Abuf[(tx * 4 + b) * 33 + tt];
                } else {
                    #pragma unroll
                    for (int b = 0; b < 4; b++) bv[b] = Bbuf[tt * 65 + tx * 4 + b];
                }
                #pragma unroll
                for (int a = 0; a < 4; a++)
                    #pragma unroll
                    for (int b = 0; b < 4; b++) acc[a][b] += av[a] * bv[b];
            }
            __syncthreads();
        }
    }
    float* out = g_part + (((size_t)mode * BH + bh) * NSPLIT + blockIdx.z) * 4096;
    #pragma unroll
    for (int a = 0; a < 4; a++)
        #pragma unroll
        for (int b = 0; b < 4; b++)
            out[(ty * 4 + a) * 64 + tx * 4 + b] = acc[a][b];
}

// fixed-order reduce of split-K partials
__global__ void k_gred(int modebase) {
    int gid = blockIdx.x * blockDim.x + threadIdx.x;
    int e = gid & 4095;
    int bh = (gid >> 12) & 63;
    int mode = modebase + (gid >> 18);
    const float* p = g_part + ((size_t)(mode * BH + bh) * NSPLIT) * 4096 + e;
    float s = p[0];
    #pragma unroll
    for (int t = 1; t < NSPLIT; t++) s += p[t * 4096];
    float* dst;
    switch (mode) { case 0: dst = g_H; break; case 1: dst = g_P; break;
                    case 2: dst = g_G; break; case 3: dst = g_RK; break;
                    default: dst = g_W; break; }
    dst[bh * 4096 + e] = s;
}

// analytic rowdot: rowdot_j = 2*((H G)_jj - sum_d P_jd RK_jd); G symmetric -> row reads.
// grid(512) x 256 : warp per row
__global__ void k_rowdotA() {
    int row = blockIdx.x * 8 + (threadIdx.x >> 5);   // 0..BH*RNK-1
    int lane = threadIdx.x & 31;
    int bh = row >> 6, j = row & 63;
    const float* Hr = g_H  + bh * 4096 + j * 64;
    const float* Gr = g_G  + bh * 4096 + j * 64;
    const float* Pr = g_P  + bh * 4096 + j * 64;
    const float* Kr = g_RK + bh * 4096 + j * 64;
    float s = Hr[lane] * Gr[lane] + Hr[lane + 32] * Gr[lane + 32]
            - Pr[lane] * Kr[lane] - Pr[lane + 32] * Kr[lane + 32];
    #pragma unroll
    for (int o = 16; o > 0; o >>= 1) s += __shfl_xor_sync(0xffffffffu, s, o);
    if (lane == 0) g_rowdot[row] = 2.0f * s;
}

// fused: d_left + PGD + re-normalize -> writes ls, invL in place. grid(64,16) x 256
__global__ void k_updateL(const float* __restrict__ q) {
    __shared__ float Gs [64 * 65];
    __shared__ float RKs[64 * 65];
    int bh = blockIdx.x;
    for (int e = threadIdx.x; e < 4096; e += 256) {
        int r0 = e >> 6, c = e & 63;
        Gs [r0 * 65 + c] = g_G [bh * 4096 + e];
        RKs[r0 * 65 + c] = g_RK[bh * 4096 + e];
    }
    __syncthreads();
    int w = threadIdx.x >> 5, lane = threadIdx.x & 31;
    for (int g = 0; g < 4; g++) {
        int i0 = blockIdx.y * 128 + w * 16 + g * 4;
        float ls0[4], ls1[4], lq0[4], lq1[4], qv0[4], qv1[4], a0[4], a1[4], b0[4], b1[4];
        #pragma unroll
        for (int r = 0; r < 4; r++) {
            int base = bh * S * RNK + (i0 + r) * RNK;
            ls0[r] = g_ls[base + lane]; ls1[r] = g_ls[base + 32 + lane];
            lq0[r] = ls0[r] * ls0[r];   lq1[r] = ls1[r] * ls1[r];
            qv0[r] = 0.125f * q[bh * S * D + (i0 + r) * D + lane];
            qv1[r] = 0.125f * q[bh * S * D + (i0 + r) * D + 32 + lane];
            a0[r] = 0.f; a1[r] = 0.f; b0[r] = 0.f; b1[r] = 0.f;
        }
        #pragma unroll 4
        for (int m = 0; m < 64; m++) {
            float x0 = Gs[m * 65 + lane], x1 = Gs[m * 65 + 32 + lane];
            #pragma unroll
            for (int r = 0; r < 4; r++) {
                float lv = (m < 32) ? __shfl_sync(0xffffffffu, lq0[r], m)
                                    : __shfl_sync(0xffffffffu, lq1[r], m - 32);
                a0[r] += lv * x0; a1[r] += lv * x1;
            }
        }
        #pragma unroll 4
        for (int d = 0; d < 64; d++) {
            float y0 = RKs[lane * 65 + d], y1 = RKs[(lane + 32) * 65 + d];
            #pragma unroll
            for (int r = 0; r < 4; r++) {
                float qq = (d < 32) ? __shfl_sync(0xffffffffu, qv0[r], d)
                                    : __shfl_sync(0xffffffffu, qv1[r], d - 32);
                b0[r] += qq * y0; b1[r] += qq * y1;
            }
        }
        #pragma unroll
        for (int r = 0; r < 4; r++) {
            int i = i0 + r, base = bh * S * RNK + i * RNK;
            float dl0 = (a0[r] - b0[r]) * 2.0f * ls0[r];
            float dl1 = (a1[r] - b1[r]) * 2.0f * ls1[r];
            float c = ls0[r] * dl0 + ls1[r] * dl1;
            #pragma unroll
            for (int o = 16; o > 0; o >>= 1) c += __shfl_xor_sync(0xffffffffu, c, o);
            float inv = g_invL[bh * S + i];
            float p0 = (inv > 0.f) ? ls0[r] / inv : ls0[r];
            float p1 = (inv > 0.f) ? ls1[r] / inv : ls1[r];
            float n0 = p0 - inv * (dl0 - ls0[r] * c);
            float n1 = p1 - inv * (dl1 - ls1[r] * c);
            float ss = n0 * n0 + n1 * n1;
            #pragma unroll
            for (int o = 16; o > 0; o >>= 1) ss += __shfl_xor_sync(0xffffffffu, ss, o);
            float nn = sqrtf(ss);
            g_ls[base + lane]      = (nn > 0.f) ? n0 / nn : n0;
            g_ls[base + 32 + lane] = (nn > 0.f) ? n1 / nn : n1;
            if (lane == 0) g_invL[bh * S + i] = (nn > 0.f) ? 1.0f / nn : 0.0f;
        }
    }
}

// fused: d_right + projection (analytic rowdot) + PGD -> writes Rp. grid(64,32) x 256
__global__ void k_updateR(const float* __restrict__ kin) {
    __shared__ float rsS[64 * 65];
    __shared__ float ks [64 * 65];
    __shared__ float sInv[64], sRd[64];
    int bh = blockIdx.x, t0 = blockIdx.y * 64;
    const float* rsb = g_rs + bh * RNK * S;
    for (int e = threadIdx.x; e < 4096; e += 256) {
        int r0 = e >> 6, c = e & 63;
        rsS[r0 * 65 + c] = rsb[r0 * S + t0 + c];
        ks [r0 * 65 + c] = kin[bh * S * D + (t0 + r0) * D + c];
    }
    if (threadIdx.x < 64) {
        sInv[threadIdx.x] = g_invR  [bh * 64 + threadIdx.x];
        sRd [threadIdx.x] = g_rowdot[bh * 64 + threadIdx.x];
    }
    __syncthreads();
    int w = threadIdx.x >> 5, lane = threadIdx.x & 31;
    for (int g = 0; g < 2; g++) {
        int jb = w * 8 + g * 4;
        float h0[4], h1[4], p0[4], p1[4], a0[4], a1[4];
        #pragma unroll
        for (int r = 0; r < 4; r++) {
            int j = jb + r;
            h0[r] = g_H[bh * 4096 + j * 64 + lane];
            h1[r] = g_H[bh * 4096 + j * 64 + 32 + lane];
            p0[r] = g_P[bh * 4096 + j * 64 + lane];
            p1[r] = g_P[bh * 4096 + j * 64 + 32 + lane];
            a0[r] = 0.f; a1[r] = 0.f;
        }
        #pragma unroll 4
        for (int m = 0; m < 64; m++) {
            float s0 = rsS[m * 65 + lane], s1 = rsS[m * 65 + 32 + lane];
            float x0 = s0 * s0, x1 = s1 * s1;
            #pragma unroll
            for (int r = 0; r < 4; r++) {
                float hv = (m < 32) ? __shfl_sync(0xffffffffu, h0[r], m)
                                    : __shfl_sync(0xffffffffu, h1[r], m - 32);
                a0[r] += hv * x0; a1[r] += hv * x1;
            }
        }
        #pragma unroll 4
        for (int d = 0; d < 64; d++) {
            float y0 = ks[lane * 65 + d], y1 = ks[(lane + 32) * 65 + d];
            #pragma unroll
            for (int r = 0; r < 4; r++) {
                float pv = (d < 32) ? __shfl_sync(0xffffffffu, p0[r], d)
                                    : __shfl_sync(0xffffffffu, p1[r], d - 32);
                a0[r] -= pv * y0; a1[r] -= pv * y1;
            }
        }
        #pragma unroll
        for (int r = 0; r < 4; r++) {
            int j = jb + r, rbase = bh * RNK * S + j * S + t0;
            float rs0 = rsS[j * 65 + lane], rs1 = rsS[j * 65 + 32 + lane];
            float dt0 = a0[r] * 2.0f * rs0, dt1 = a1[r] * 2.0f * rs1;
            float inv = sInv[j], rd = sRd[j];
            float pp0 = (inv > 0.f) ? rs0 / inv : rs0;
            float pp1 = (inv > 0.f) ? rs1 / inv : rs1;
            g_Rp[rbase + lane]      = pp0 - inv * (dt0 - rs0 * rd);
            g_Rp[rbase + 32 + lane] = pp1 - inv * (dt1 - rs1 * rd);
        }
    }
}

// out = lsq^2 @ W. grid(64,16) x 256
__global__ void k_out(float* __restrict__ out) {
    __shared__ float Ws[64 * 65];
    int bh = blockIdx.x;
    for (int e = threadIdx.x; e < 4096; e += 256)
        Ws[(e >> 6) * 65 + (e & 63)] = g_W[bh * 4096 + e];
    __syncthreads();
    int w = threadIdx.x >> 5, lane = threadIdx.x & 31;
    for (int g = 0; g < 4; g++) {
        int i0 = blockIdx.y * 128 + w * 16 + g * 4;
        float lq0[4], lq1[4], o0[4], o1[4];
        #pragma unroll
        for (int r = 0; r < 4; r++) {
            int base = bh * S * RNK + (i0 + r) * RNK;
            float a = g_ls[base + lane], b = g_ls[base + 32 + lane];
            lq0[r] = a * a; lq1[r] = b * b;
            o0[r] = 0.f; o1[r] = 0.f;
        }
        #pragma unroll 4
        for (int j = 0; j < 64; j++) {
            float x0 = Ws[j * 65 + lane], x1 = Ws[j * 65 + 32 + lane];
            #pragma unroll
            for (int r = 0; r < 4; r++) {
                float lv = (j < 32) ? __shfl_sync(0xffffffffu, lq0[r], j)
                                    : __shfl_sync(0xffffffffu, lq1[r], j - 32);
                o0[r] += lv * x0; o1[r] += lv * x1;
            }
        }
        #pragma unroll
        for (int r = 0; r < 4; r++) {
            int ob = bh * S * D + (i0 + r) * D;
            out[ob + lane]      = o0[r];
            out[ob + 32 + lane] = o1[r];
        }
    }
}

extern "C" void kernel_launch(void* const* d_in, const int* in_sizes, int n_in,
                              void* d_out, int out_size) {
    const float* q = (const float*)d_in[0];
    const float* k = (const float*)d_in[1];
    const float* v = (const float*)d_in[2];
    float* out = (float*)d_out;

    uint32_t k1a, k1b, k2a, k2b;
#if JAX_PARTITIONABLE
    tf2x32(0u, 42u, 0u, 0u, &k1a, &k1b);
    tf2x32(0u, 42u, 0u, 1u, &k2a, &k2b);
#else
    { uint32_t a0, b0, a1, b1;
      tf2x32(0u, 42u, 0u, 2u, &a0, &b0);
      tf2x32(0u, 42u, 1u, 3u, &a1, &b1);
      k1a = a0; k1b = a1; k2a = b0; k2b = b1; }
#endif

    k_initL<<<BH * S / 8, 256>>>(k1a, k1b);
    k_initR<<<NELEM / 4 / 256, 256>>>(k2a, k2b);
    k_prepR<<<dim3(BH, 64), 256>>>();
    for (int step = 0; step < 8; step++) {
        k_gemm64<<<dim3(BH, 4, NSPLIT), 256>>>(q, k, v, 0);   // H, P, G, RK partials
        k_gred<<<4 * BH * 4096 / 256, 256>>>(0);
        k_rowdotA<<<BH * RNK / 8, 256>>>();
        k_updateL<<<dim3(BH, 16), 256>>>(q);
        k_updateR<<<dim3(BH, 32), 256>>>(k);
        k_prepR<<<dim3(BH, 64), 256>>>();
    }
    k_gemm64<<<dim3(BH, 1, NSPLIT), 256>>>(q, k, v, 4);       // W partials
    k_gred<<<BH * 4096 / 256, 256>>>(4);
    k_out<<<dim3(BH, 16), 256>>>(out);
}

// round 11
// speedup vs baseline: 1.5860x; 1.1693x over previous
#include <cuda_runtime.h>
#include <cstdint>

#define BH   64
#define S    2048
#define RNK  64
#define D    64
#define NELEM (BH*S*RNK)
#define NSPLIT 8

#define JAX_PARTITIONABLE 1

__device__ __align__(16) float g_Rp  [NELEM];
__device__ __align__(16) float g_ls  [NELEM];
__device__ __align__(16) float g_rs  [NELEM];
__device__ __align__(16) float g_part[5*BH*NSPLIT*4096];
__device__ float g_invL[BH*S];
__device__ float g_invR[BH*RNK];
__device__ float g_rowdot[BH*RNK];
__device__ float g_G [BH*RNK*RNK];
__device__ float g_H [BH*RNK*RNK];
__device__ float g_P [BH*RNK*D];
__device__ float g_RK[BH*RNK*D];
__device__ float g_W [BH*RNK*D];

__host__ __device__ inline uint32_t rotl_(uint32_t x, int r) {
#ifdef __CUDA_ARCH__
    return __funnelshift_l(x, x, r);
#else
    return (x << r) | (x >> (32 - r));
#endif
}

__host__ __device__ inline void tf2x32(uint32_t k0, uint32_t k1,
                                       uint32_t x0, uint32_t x1,
                                       uint32_t* o0, uint32_t* o1) {
    uint32_t ks0 = k0, ks1 = k1, ks2 = k0 ^ k1 ^ 0x1BD11BDAu;
    x0 += ks0; x1 += ks1;
#define TF_RND(r) { x0 += x1; x1 = rotl_(x1, r); x1 ^= x0; }
    TF_RND(13) TF_RND(15) TF_RND(26) TF_RND(6)
    x0 += ks1; x1 += ks2 + 1u;
    TF_RND(17) TF_RND(29) TF_RND(16) TF_RND(24)
    x0 += ks2; x1 += ks0 + 2u;
    TF_RND(13) TF_RND(15) TF_RND(26) TF_RND(6)
    x0 += ks0; x1 += ks1 + 3u;
    TF_RND(17) TF_RND(29) TF_RND(16) TF_RND(24)
    x0 += ks1; x1 += ks2 + 4u;
    TF_RND(13) TF_RND(15) TF_RND(26) TF_RND(6)
    x0 += ks2; x1 += ks0 + 5u;
#undef TF_RND
    *o0 = x0; *o1 = x1;
}

__device__ inline float bits_to_unit(uint32_t bits) {
    return __uint_as_float((bits >> 9) | 0x3F800000u) - 1.0f;
}

__device__ inline uint32_t rbits(uint32_t ka, uint32_t kb, uint32_t idx) {
    uint32_t o0, o1;
#if JAX_PARTITIONABLE
    tf2x32(ka, kb, 0u, idx, &o0, &o1);
    return o0 ^ o1;
#else
    const uint32_t HN = NELEM / 2;
    if (idx < HN) { tf2x32(ka, kb, idx, idx + HN, &o0, &o1); return o0; }
    tf2x32(ka, kb, idx - HN, idx, &o0, &o1); return o1;
#endif
}

__global__ void k_initL(uint32_t la, uint32_t lb) {
    int row = blockIdx.x * 8 + (threadIdx.x >> 5);
    int lane = threadIdx.x & 31;
    int base = row * RNK;
    float u0 = bits_to_unit(rbits(la, lb, (uint32_t)(base + lane)));
    float u1 = bits_to_unit(rbits(la, lb, (uint32_t)(base + 32 + lane)));
    float v0 = 0.125f + (0.002f * u0 - 0.001f);
    float v1 = 0.125f + (0.002f * u1 - 0.001f);
    float ss = v0 * v0 + v1 * v1;
    #pragma unroll
    for (int o = 16; o > 0; o >>= 1) ss += __shfl_xor_sync(0xffffffffu, ss, o);
    float n = sqrtf(ss);
    float inv = (n > 0.f) ? (1.0f / n) : 0.0f;
    g_ls[base + lane]      = (n > 0.f) ? v0 / n : v0;
    g_ls[base + 32 + lane] = (n > 0.f) ? v1 / n : v1;
    if (lane == 0) g_invL[row] = inv;
}

__global__ void k_initR(uint32_t ra, uint32_t rb) {
    int g4 = blockIdx.x * blockDim.x + threadIdx.x;
    int e = g4 * 4;
    float4 o;
    o.x = 0.022097086912079608f + (0.002f * bits_to_unit(rbits(ra, rb, e))     - 0.001f);
    o.y = 0.022097086912079608f + (0.002f * bits_to_unit(rbits(ra, rb, e + 1)) - 0.001f);
    o.z = 0.022097086912079608f + (0.002f * bits_to_unit(rbits(ra, rb, e + 2)) - 0.001f);
    o.w = 0.022097086912079608f + (0.002f * bits_to_unit(rbits(ra, rb, e + 3)) - 0.001f);
    ((float4*)g_Rp)[g4] = o;
}

__global__ void k_prepR() {
    int bh = blockIdx.x, j = blockIdx.y;
    int base = bh * RNK * S + j * S;
    int tid = threadIdx.x;
    float v[8]; float ss = 0.f;
    #pragma unroll
    for (int p = 0; p < 8; p++) { v[p] = g_Rp[base + p * 256 + tid]; ss += v[p] * v[p]; }
    #pragma unroll
    for (int o = 16; o > 0; o >>= 1) ss += __shfl_xor_sync(0xffffffffu, ss, o);
    __shared__ float red[8];
    if ((tid & 31) == 0) red[tid >> 5] = ss;
    __syncthreads();
    float n = sqrtf(red[0]+red[1]+red[2]+red[3]+red[4]+red[5]+red[6]+red[7]);
    float inv = (n > 0.f) ? (1.0f / n) : 0.0f;
    #pragma unroll
    for (int p = 0; p < 8; p++)
        g_rs[base + p * 256 + tid] = (n > 0.f) ? v[p] / n : v[p];
    if (tid == 0) g_invR[bh * RNK + j] = inv;
}

// Fused-pair split-K gemm. pair 0: H|P (A=lsq^2, B right=q/8). pair 1: G|RK
// (A=rsq^T, B right=k). pair 2: -|W (A=rsq^T, B right=v; left half not stored).
// grid(BH, npairs, NSPLIT) x 128, 8x8 register tiles, out 64x128.
__global__ void k_gemmF(const float* __restrict__ q, const float* __restrict__ kin,
                        const float* __restrict__ vin, int ybase) {
    __shared__ __align__(16) float buf[32 * 132];
    int bh = blockIdx.x, pair = ybase + blockIdx.y, kz = blockIdx.z;
    int tid = threadIdx.x;
    int ty = tid >> 4, tx = tid & 15;          // ty 0..7 rows, tx 0..15 cols
    int kbeg = kz * (S / NSPLIT);
    float acc[8][8];
    #pragma unroll
    for (int a = 0; a < 8; a++)
        #pragma unroll
        for (int b = 0; b < 8; b++) acc[a][b] = 0.f;

    const float* rhs = (pair == 0) ? (q + bh * S * D)
                     : (pair == 1) ? (kin + bh * S * D)
                                   : (vin + bh * S * D);
    float rscale = (pair == 0) ? 0.125f : 1.0f;

    for (int t0 = kbeg; t0 < kbeg + S / NSPLIT; t0 += 32) {
        if (pair == 0) {
            const float* lsb = g_ls + bh * S * RNK;
            #pragma unroll
            for (int p = 0; p < 8; p++) {
                int idx = p * 128 + tid;
                int row = idx >> 5, c4 = idx & 31;
                if (c4 < 16) {
                    float4 x = *reinterpret_cast<const float4*>(&lsb[(t0 + row) * RNK + c4 * 4]);
                    x.x *= x.x; x.y *= x.y; x.z *= x.z; x.w *= x.w;
                    *reinterpret_cast<float4*>(&buf[row * 132 + c4 * 4]) = x;
                } else {
                    float4 x = *reinterpret_cast<const float4*>(&rhs[(t0 + row) * D + (c4 - 16) * 4]);
                    x.x *= rscale; x.y *= rscale; x.z *= rscale; x.w *= rscale;
                    *reinterpret_cast<float4*>(&buf[row * 132 + 64 + (c4 - 16) * 4]) = x;
                }
            }
        } else {
            const float* rsb = g_rs + bh * RNK * S;
            // transpose fill: cols 0-63 = rsq^T
            #pragma unroll
            for (int p = 0; p < 16; p++) {
                int idx = p * 128 + tid;
                int j = idx >> 5, tt = idx & 31;
                float x = rsb[j * S + t0 + tt];
                buf[tt * 132 + j] = x * x;
            }
            // cols 64-127 = k or v
            #pragma unroll
            for (int p = 0; p < 4; p++) {
                int idx = p * 128 + tid;
                int row = idx >> 4, c4 = idx & 15;
                float4 x = *reinterpret_cast<const float4*>(&rhs[(t0 + row) * D + c4 * 4]);
                *reinterpret_cast<float4*>(&buf[row * 132 + 64 + c4 * 4]) = x;
            }
        }
        __syncthreads();
        #pragma unroll 4
        for (int kk = 0; kk < 32; kk++) {
            float4 a0 = *reinterpret_cast<const float4*>(&buf[kk * 132 + ty * 8]);
            float4 a1 = *reinterpret_cast<const float4*>(&buf[kk * 132 + ty * 8 + 4]);
            float4 b0 = *reinterpret_cast<const float4*>(&buf[kk * 132 + tx * 8]);
            float4 b1 = *reinterpret_cast<const float4*>(&buf[kk * 132 + tx * 8 + 4]);
            float av[8] = {a0.x,a0.y,a0.z,a0.w,a1.x,a1.y,a1.z,a1.w};
            float bv[8] = {b0.x,b0.y,b0.z,b0.w,b1.x,b1.y,b1.z,b1.w};
            #pragma unroll
            for (int a = 0; a < 8; a++)
                #pragma unroll
                for (int b = 0; b < 8; b++) acc[a][b] += av[a] * bv[b];
        }
        __syncthreads();
    }

    // each thread's 8 cols lie entirely in one half (tx<8 -> left, tx>=8 -> right)
    int right = (tx >= 8);
    int mode = (pair == 0) ? (right ? 1 : 0)
             : (pair == 1) ? (right ? 3 : 2)
                           : 4;                       // pair 2 right half = W
    if (pair == 2 && !right) return;
    int cloc = (tx & 7) * 8;
    float* out = g_part + (((size_t)mode * BH + bh) * NSPLIT + kz) * 4096;
    #pragma unroll
    for (int a = 0; a < 8; a++) {
        int j = ty * 8 + a;
        float4 o0 = make_float4(acc[a][0], acc[a][1], acc[a][2], acc[a][3]);
        float4 o1 = make_float4(acc[a][4], acc[a][5], acc[a][6], acc[a][7]);
        *reinterpret_cast<float4*>(&out[j * 64 + cloc])     = o0;
        *reinterpret_cast<float4*>(&out[j * 64 + cloc + 4]) = o1;
    }
}

// fixed-order reduce of split-K partials
__global__ void k_gred(int modebase) {
    int gid = blockIdx.x * blockDim.x + threadIdx.x;
    int e = gid & 4095;
    int bh = (gid >> 12) & 63;
    int mode = modebase + (gid >> 18);
    const float* p = g_part + ((size_t)(mode * BH + bh) * NSPLIT) * 4096 + e;
    float s = p[0];
    #pragma unroll
    for (int t = 1; t < NSPLIT; t++) s += p[t * 4096];
    float* dst;
    switch (mode) { case 0: dst = g_H; break; case 1: dst = g_P; break;
                    case 2: dst = g_G; break; case 3: dst = g_RK; break;
                    default: dst = g_W; break; }
    dst[bh * 4096 + e] = s;
}

// analytic rowdot: rowdot_j = 2*((H G)_jj - sum_d P_jd RK_jd)
__global__ void k_rowdotA() {
    int row = blockIdx.x * 8 + (threadIdx.x >> 5);
    int lane = threadIdx.x & 31;
    int bh = row >> 6, j = row & 63;
    const float* Hr = g_H  + bh * 4096 + j * 64;
    const float* Gr = g_G  + bh * 4096 + j * 64;
    const float* Pr = g_P  + bh * 4096 + j * 64;
    const float* Kr = g_RK + bh * 4096 + j * 64;
    float s = Hr[lane] * Gr[lane] + Hr[lane + 32] * Gr[lane + 32]
            - Pr[lane] * Kr[lane] - Pr[lane + 32] * Kr[lane + 32];
    #pragma unroll
    for (int o = 16; o > 0; o >>= 1) s += __shfl_xor_sync(0xffffffffu, s, o);
    if (lane == 0) g_rowdot[row] = 2.0f * s;
}

// fused: d_left + PGD + re-normalize -> writes ls, invL in place. grid(64,16) x 256
__global__ void k_updateL(const float* __restrict__ q) {
    __shared__ float Gs [64 * 65];
    __shared__ float RKs[64 * 65];
    int bh = blockIdx.x;
    for (int e = threadIdx.x; e < 4096; e += 256) {
        int r0 = e >> 6, c = e & 63;
        Gs [r0 * 65 + c] = g_G [bh * 4096 + e];
        RKs[r0 * 65 + c] = g_RK[bh * 4096 + e];
    }
    __syncthreads();
    int w = threadIdx.x >> 5, lane = threadIdx.x & 31;
    for (int g = 0; g < 4; g++) {
        int i0 = blockIdx.y * 128 + w * 16 + g * 4;
        float ls0[4], ls1[4], lq0[4], lq1[4], qv0[4], qv1[4], a0[4], a1[4], b0[4], b1[4];
        #pragma unroll
        for (int r = 0; r < 4; r++) {
            int base = bh * S * RNK + (i0 + r) * RNK;
            ls0[r] = g_ls[base + lane]; ls1[r] = g_ls[base + 32 + lane];
            lq0[r] = ls0[r] * ls0[r];   lq1[r] = ls1[r] * ls1[r];
            qv0[r] = 0.125f * q[bh * S * D + (i0 + r) * D + lane];
            qv1[r] = 0.125f * q[bh * S * D + (i0 + r) * D + 32 + lane];
            a0[r] = 0.f; a1[r] = 0.f; b0[r] = 0.f; b1[r] = 0.f;
        }
        #pragma unroll 4
        for (int m = 0; m < 64; m++) {
            float x0 = Gs[m * 65 + lane], x1 = Gs[m * 65 + 32 + lane];
            #pragma unroll
            for (int r = 0; r < 4; r++) {
                float lv = (m < 32) ? __shfl_sync(0xffffffffu, lq0[r], m)
                                    : __shfl_sync(0xffffffffu, lq1[r], m - 32);
                a0[r] += lv * x0; a1[r] += lv * x1;
            }
        }
        #pragma unroll 4
        for (int d = 0; d < 64; d++) {
            float y0 = RKs[lane * 65 + d], y1 = RKs[(lane + 32) * 65 + d];
            #pragma unroll
            for (int r = 0; r < 4; r++) {
                float qq = (d < 32) ? __shfl_sync(0xffffffffu, qv0[r], d)
                                    : __shfl_sync(0xffffffffu, qv1[r], d - 32);
                b0[r] += qq * y0; b1[r] += qq * y1;
            }
        }
        #pragma unroll
        for (int r = 0; r < 4; r++) {
            int i = i0 + r, base = bh * S * RNK + i * RNK;
            float dl0 = (a0[r] - b0[r]) * 2.0f * ls0[r];
            float dl1 = (a1[r] - b1[r]) * 2.0f * ls1[r];
            float c = ls0[r] * dl0 + ls1[r] * dl1;
            #pragma unroll
            for (int o = 16; o > 0; o >>= 1) c += __shfl_xor_sync(0xffffffffu, c, o);
            float inv = g_invL[bh * S + i];
            float p0 = (inv > 0.f) ? ls0[r] / inv : ls0[r];
            float p1 = (inv > 0.f) ? ls1[r] / inv : ls1[r];
            float n0 = p0 - inv * (dl0 - ls0[r] * c);
            float n1 = p1 - inv * (dl1 - ls1[r] * c);
            float ss = n0 * n0 + n1 * n1;
            #pragma unroll
            for (int o = 16; o > 0; o >>= 1) ss += __shfl_xor_sync(0xffffffffu, ss, o);
            float nn = sqrtf(ss);
            g_ls[base + lane]      = (nn > 0.f) ? n0 / nn : n0;
            g_ls[base + 32 + lane] = (nn > 0.f) ? n1 / nn : n1;
            if (lane == 0) g_invL[bh * S + i] = (nn > 0.f) ? 1.0f / nn : 0.0f;
        }
    }
}

// fused: d_right + projection + PGD -> writes Rp. grid(64,32) x 256
__global__ void k_updateR(const float* __restrict__ kin) {
    __shared__ float rsS[64 * 65];
    __shared__ float ks [64 * 65];
    __shared__ float sInv[64], sRd[64];
    int bh = blockIdx.x, t0 = blockIdx.y * 64;
    const float* rsb = g_rs + bh * RNK * S;
    for (int e = threadIdx.x; e < 4096; e += 256) {
        int r0 = e >> 6, c = e & 63;
        rsS[r0 * 65 + c] = rsb[r0 * S + t0 + c];
        ks [r0 * 65 + c] = kin[bh * S * D + (t0 + r0) * D + c];
    }
    if (threadIdx.x < 64) {
        sInv[threadIdx.x] = g_invR  [bh * 64 + threadIdx.x];
        sRd [threadIdx.x] = g_rowdot[bh * 64 + threadIdx.x];
    }
    __syncthreads();
    int w = threadIdx.x >> 5, lane = threadIdx.x & 31;
    for (int g = 0; g < 2; g++) {
        int jb = w * 8 + g * 4;
        float h0[4], h1[4], p0[4], p1[4], a0[4], a1[4];
        #pragma unroll
        for (int r = 0; r < 4; r++) {
            int j = jb + r;
            h0[r] = g_H[bh * 4096 + j * 64 + lane];
            h1[r] = g_H[bh * 4096 + j * 64 + 32 + lane];
            p0[r] = g_P[bh * 4096 + j * 64 + lane];
            p1[r] = g_P[bh * 4096 + j * 64 + 32 + lane];
            a0[r] = 0.f; a1[r] = 0.f;
        }
        #pragma unroll 4
        for (int m = 0; m < 64; m++) {
            float s0 = rsS[m * 65 + lane], s1 = rsS[m * 65 + 32 + lane];
            float x0 = s0 * s0, x1 = s1 * s1;
            #pragma unroll
            for (int r = 0; r < 4; r++) {
                float hv = (m < 32) ? __shfl_sync(0xffffffffu, h0[r], m)
                                    : __shfl_sync(0xffffffffu, h1[r], m - 32);
                a0[r] += hv * x0; a1[r] += hv * x1;
            }
        }
        #pragma unroll 4
        for (int d = 0; d < 64; d++) {
            float y0 = ks[lane * 65 + d], y1 = ks[(lane + 32) * 65 + d];
            #pragma unroll
            for (int r = 0; r < 4; r++) {
                float pv = (d < 32) ? __shfl_sync(0xffffffffu, p0[r], d)
                                    : __shfl_sync(0xffffffffu, p1[r], d - 32);
                a0[r] -= pv * y0; a1[r] -= pv * y1;
            }
        }
        #pragma unroll
        for (int r = 0; r < 4; r++) {
            int j = jb + r, rbase = bh * RNK * S + j * S + t0;
            float rs0 = rsS[j * 65 + lane], rs1 = rsS[j * 65 + 32 + lane];
            float dt0 = a0[r] * 2.0f * rs0, dt1 = a1[r] * 2.0f * rs1;
            float inv = sInv[j], rd = sRd[j];
            float pp0 = (inv > 0.f) ? rs0 / inv : rs0;
            float pp1 = (inv > 0.f) ? rs1 / inv : rs1;
            g_Rp[rbase + lane]      = pp0 - inv * (dt0 - rs0 * rd);
            g_Rp[rbase + 32 + lane] = pp1 - inv * (dt1 - rs1 * rd);
        }
    }
}

// out = lsq^2 @ W. grid(64,16) x 256
__global__ void k_out(float* __restrict__ out) {
    __shared__ float Ws[64 * 65];
    int bh = blockIdx.x;
    for (int e = threadIdx.x; e < 4096; e += 256)
        Ws[(e >> 6) * 65 + (e & 63)] = g_W[bh * 4096 + e];
    __syncthreads();
    int w = threadIdx.x >> 5, lane = threadIdx.x & 31;
    for (int g = 0; g < 4; g++) {
        int i0 = blockIdx.y * 128 + w * 16 + g * 4;
        float lq0[4], lq1[4], o0[4], o1[4];
        #pragma unroll
        for (int r = 0; r < 4; r++) {
            int base = bh * S * RNK + (i0 + r) * RNK;
            float a = g_ls[base + lane], b = g_ls[base + 32 + lane];
            lq0[r] = a * a; lq1[r] = b * b;
            o0[r] = 0.f; o1[r] = 0.f;
        }
        #pragma unroll 4
        for (int j = 0; j < 64; j++) {
            float x0 = Ws[j * 65 + lane], x1 = Ws[j * 65 + 32 + lane];
            #pragma unroll
            for (int r = 0; r < 4; r++) {
                float lv = (j < 32) ? __shfl_sync(0xffffffffu, lq0[r], j)
                                    : __shfl_sync(0xffffffffu, lq1[r], j - 32);
                o0[r] += lv * x0; o1[r] += lv * x1;
            }
        }
        #pragma unroll
        for (int r = 0; r < 4; r++) {
            int ob = bh * S * D + (i0 + r) * D;
            out[ob + lane]      = o0[r];
            out[ob + 32 + lane] = o1[r];
        }
    }
}

extern "C" void kernel_launch(void* const* d_in, const int* in_sizes, int n_in,
                              void* d_out, int out_size) {
    const float* q = (const float*)d_in[0];
    const float* k = (const float*)d_in[1];
    const float* v = (const float*)d_in[2];
    float* out = (float*)d_out;

    uint32_t k1a, k1b, k2a, k2b;
#if JAX_PARTITIONABLE
    tf2x32(0u, 42u, 0u, 0u, &k1a, &k1b);
    tf2x32(0u, 42u, 0u, 1u, &k2a, &k2b);
#else
    { uint32_t a0, b0, a1, b1;
      tf2x32(0u, 42u, 0u, 2u, &a0, &b0);
      tf2x32(0u, 42u, 1u, 3u, &a1, &b1);
      k1a = a0; k1b = a1; k2a = b0; k2b = b1; }
#endif

    k_initL<<<BH * S / 8, 256>>>(k1a, k1b);
    k_initR<<<NELEM / 4 / 256, 256>>>(k2a, k2b);
    k_prepR<<<dim3(BH, 64), 256>>>();
    for (int step = 0; step < 8; step++) {
        k_gemmF<<<dim3(BH, 2, NSPLIT), 128>>>(q, k, v, 0);    // H|P and G|RK partials
        k_gred<<<4 * BH * 4096 / 256, 256>>>(0);
        k_rowdotA<<<BH * RNK / 8, 256>>>();
        k_updateL<<<dim3(BH, 16), 256>>>(q);
        k_updateR<<<dim3(BH, 32), 256>>>(k);
        k_prepR<<<dim3(BH, 64), 256>>>();
    }
    k_gemmF<<<dim3(BH, 1, NSPLIT), 128>>>(q, k, v, 2);        // W partials
    k_gred<<<BH * 4096 / 256, 256>>>(4);
    k_out<<<dim3(BH, 16), 256>>>(out);
}

// round 13
// speedup vs baseline: 1.8901x; 1.1917x over previous
#include <cuda_runtime.h>
#include <cstdint>

#define BH   64
#define S    2048
#define RNK  64
#define D    64
#define NELEM (BH*S*RNK)
#define NSPLIT 8

#define JAX_PARTITIONABLE 1

__device__ __align__(16) float g_Rp  [NELEM];
__device__ __align__(16) float g_ls  [NELEM];
__device__ __align__(16) float g_rs  [NELEM];
__device__ __align__(16) float g_part[5*BH*NSPLIT*4096];
__device__ float g_invL[BH*S];
__device__ float g_invR[BH*RNK];
__device__ float g_rowdot[BH*RNK];
__device__ float g_G [BH*RNK*RNK];
__device__ float g_H [BH*RNK*RNK];
__device__ float g_P [BH*RNK*D];
__device__ float g_RK[BH*RNK*D];
__device__ float g_W [BH*RNK*D];

__host__ __device__ inline uint32_t rotl_(uint32_t x, int r) {
#ifdef __CUDA_ARCH__
    return __funnelshift_l(x, x, r);
#else
    return (x << r) | (x >> (32 - r));
#endif
}

__host__ __device__ inline void tf2x32(uint32_t k0, uint32_t k1,
                                       uint32_t x0, uint32_t x1,
                                       uint32_t* o0, uint32_t* o1) {
    uint32_t ks0 = k0, ks1 = k1, ks2 = k0 ^ k1 ^ 0x1BD11BDAu;
    x0 += ks0; x1 += ks1;
#define TF_RND(r) { x0 += x1; x1 = rotl_(x1, r); x1 ^= x0; }
    TF_RND(13) TF_RND(15) TF_RND(26) TF_RND(6)
    x0 += ks1; x1 += ks2 + 1u;
    TF_RND(17) TF_RND(29) TF_RND(16) TF_RND(24)
    x0 += ks2; x1 += ks0 + 2u;
    TF_RND(13) TF_RND(15) TF_RND(26) TF_RND(6)
    x0 += ks0; x1 += ks1 + 3u;
    TF_RND(17) TF_RND(29) TF_RND(16) TF_RND(24)
    x0 += ks1; x1 += ks2 + 4u;
    TF_RND(13) TF_RND(15) TF_RND(26) TF_RND(6)
    x0 += ks2; x1 += ks0 + 5u;
#undef TF_RND
    *o0 = x0; *o1 = x1;
}

__device__ inline float bits_to_unit(uint32_t bits) {
    return __uint_as_float((bits >> 9) | 0x3F800000u) - 1.0f;
}

__device__ inline uint32_t rbits(uint32_t ka, uint32_t kb, uint32_t idx) {
    uint32_t o0, o1;
#if JAX_PARTITIONABLE
    tf2x32(ka, kb, 0u, idx, &o0, &o1);
    return o0 ^ o1;
#else
    const uint32_t HN = NELEM / 2;
    if (idx < HN) { tf2x32(ka, kb, idx, idx + HN, &o0, &o1); return o0; }
    tf2x32(ka, kb, idx - HN, idx, &o0, &o1); return o1;
#endif
}

__global__ void k_initL(uint32_t la, uint32_t lb) {
    int row = blockIdx.x * 8 + (threadIdx.x >> 5);
    int lane = threadIdx.x & 31;
    int base = row * RNK;
    float u0 = bits_to_unit(rbits(la, lb, (uint32_t)(base + lane)));
    float u1 = bits_to_unit(rbits(la, lb, (uint32_t)(base + 32 + lane)));
    float v0 = 0.125f + (0.002f * u0 - 0.001f);
    float v1 = 0.125f + (0.002f * u1 - 0.001f);
    float ss = v0 * v0 + v1 * v1;
    #pragma unroll
    for (int o = 16; o > 0; o >>= 1) ss += __shfl_xor_sync(0xffffffffu, ss, o);
    float n = sqrtf(ss);
    float inv = (n > 0.f) ? (1.0f / n) : 0.0f;
    g_ls[base + lane]      = (n > 0.f) ? v0 / n : v0;
    g_ls[base + 32 + lane] = (n > 0.f) ? v1 / n : v1;
    if (lane == 0) g_invL[row] = inv;
}

__global__ void k_initR(uint32_t ra, uint32_t rb) {
    int g4 = blockIdx.x * blockDim.x + threadIdx.x;
    int e = g4 * 4;
    float4 o;
    o.x = 0.022097086912079608f + (0.002f * bits_to_unit(rbits(ra, rb, e))     - 0.001f);
    o.y = 0.022097086912079608f + (0.002f * bits_to_unit(rbits(ra, rb, e + 1)) - 0.001f);
    o.z = 0.022097086912079608f + (0.002f * bits_to_unit(rbits(ra, rb, e + 2)) - 0.001f);
    o.w = 0.022097086912079608f + (0.002f * bits_to_unit(rbits(ra, rb, e + 3)) - 0.001f);
    ((float4*)g_Rp)[g4] = o;
}

__global__ void k_prepR() {
    int bh = blockIdx.x, j = blockIdx.y;
    int base = bh * RNK * S + j * S;
    int tid = threadIdx.x;
    float v[8]; float ss = 0.f;
    #pragma unroll
    for (int p = 0; p < 8; p++) { v[p] = g_Rp[base + p * 256 + tid]; ss += v[p] * v[p]; }
    #pragma unroll
    for (int o = 16; o > 0; o >>= 1) ss += __shfl_xor_sync(0xffffffffu, ss, o);
    __shared__ float red[8];
    if ((tid & 31) == 0) red[tid >> 5] = ss;
    __syncthreads();
    float n = sqrtf(red[0]+red[1]+red[2]+red[3]+red[4]+red[5]+red[6]+red[7]);
    float inv = (n > 0.f) ? (1.0f / n) : 0.0f;
    #pragma unroll
    for (int p = 0; p < 8; p++)
        g_rs[base + p * 256 + tid] = (n > 0.f) ? v[p] / n : v[p];
    if (tid == 0) g_invR[bh * RNK + j] = inv;
}

// Fused-pair split-K gemm (unchanged from R11).
__global__ void k_gemmF(const float* __restrict__ q, const float* __restrict__ kin,
                        const float* __restrict__ vin, int ybase) {
    __shared__ __align__(16) float buf[32 * 132];
    int bh = blockIdx.x, pair = ybase + blockIdx.y, kz = blockIdx.z;
    int tid = threadIdx.x;
    int ty = tid >> 4, tx = tid & 15;
    int kbeg = kz * (S / NSPLIT);
    float acc[8][8];
    #pragma unroll
    for (int a = 0; a < 8; a++)
        #pragma unroll
        for (int b = 0; b < 8; b++) acc[a][b] = 0.f;

    const float* rhs = (pair == 0) ? (q + bh * S * D)
                     : (pair == 1) ? (kin + bh * S * D)
                                   : (vin + bh * S * D);
    float rscale = (pair == 0) ? 0.125f : 1.0f;

    for (int t0 = kbeg; t0 < kbeg + S / NSPLIT; t0 += 32) {
        if (pair == 0) {
            const float* lsb = g_ls + bh * S * RNK;
            #pragma unroll
            for (int p = 0; p < 8; p++) {
                int idx = p * 128 + tid;
                int row = idx >> 5, c4 = idx & 31;
                if (c4 < 16) {
                    float4 x = *reinterpret_cast<const float4*>(&lsb[(t0 + row) * RNK + c4 * 4]);
                    x.x *= x.x; x.y *= x.y; x.z *= x.z; x.w *= x.w;
                    *reinterpret_cast<float4*>(&buf[row * 132 + c4 * 4]) = x;
                } else {
                    float4 x = *reinterpret_cast<const float4*>(&rhs[(t0 + row) * D + (c4 - 16) * 4]);
                    x.x *= rscale; x.y *= rscale; x.z *= rscale; x.w *= rscale;
                    *reinterpret_cast<float4*>(&buf[row * 132 + 64 + (c4 - 16) * 4]) = x;
                }
            }
        } else {
            const float* rsb = g_rs + bh * RNK * S;
            #pragma unroll
            for (int p = 0; p < 16; p++) {
                int idx = p * 128 + tid;
                int j = idx >> 5, tt = idx & 31;
                float x = rsb[j * S + t0 + tt];
                buf[tt * 132 + j] = x * x;
            }
            #pragma unroll
            for (int p = 0; p < 4; p++) {
                int idx = p * 128 + tid;
                int row = idx >> 4, c4 = idx & 15;
                float4 x = *reinterpret_cast<const float4*>(&rhs[(t0 + row) * D + c4 * 4]);
                *reinterpret_cast<float4*>(&buf[row * 132 + 64 + c4 * 4]) = x;
            }
        }
        __syncthreads();
        #pragma unroll 4
        for (int kk = 0; kk < 32; kk++) {
            float4 a0 = *reinterpret_cast<const float4*>(&buf[kk * 132 + ty * 8]);
            float4 a1 = *reinterpret_cast<const float4*>(&buf[kk * 132 + ty * 8 + 4]);
            float4 b0 = *reinterpret_cast<const float4*>(&buf[kk * 132 + tx * 8]);
            float4 b1 = *reinterpret_cast<const float4*>(&buf[kk * 132 + tx * 8 + 4]);
            float av[8] = {a0.x,a0.y,a0.z,a0.w,a1.x,a1.y,a1.z,a1.w};
            float bv[8] = {b0.x,b0.y,b0.z,b0.w,b1.x,b1.y,b1.z,b1.w};
            #pragma unroll
            for (int a = 0; a < 8; a++)
                #pragma unroll
                for (int b = 0; b < 8; b++) acc[a][b] += av[a] * bv[b];
        }
        __syncthreads();
    }

    int right = (tx >= 8);
    int mode = (pair == 0) ? (right ? 1 : 0)
             : (pair == 1) ? (right ? 3 : 2)
                           : 4;
    if (pair == 2 && !right) return;
    int cloc = (tx & 7) * 8;
    float* out = g_part + (((size_t)mode * BH + bh) * NSPLIT + kz) * 4096;
    #pragma unroll
    for (int a = 0; a < 8; a++) {
        int j = ty * 8 + a;
        *reinterpret_cast<float4*>(&out[j * 64 + cloc])     = make_float4(acc[a][0], acc[a][1], acc[a][2], acc[a][3]);
        *reinterpret_cast<float4*>(&out[j * 64 + cloc + 4]) = make_float4(acc[a][4], acc[a][5], acc[a][6], acc[a][7]);
    }
}

__global__ void k_gred(int modebase) {
    int gid = blockIdx.x * blockDim.x + threadIdx.x;
    int e = gid & 4095;
    int bh = (gid >> 12) & 63;
    int mode = modebase + (gid >> 18);
    const float* p = g_part + ((size_t)(mode * BH + bh) * NSPLIT) * 4096 + e;
    float s = p[0];
    #pragma unroll
    for (int t = 1; t < NSPLIT; t++) s += p[t * 4096];
    float* dst;
    switch (mode) { case 0: dst = g_H; break; case 1: dst = g_P; break;
                    case 2: dst = g_G; break; case 3: dst = g_RK; break;
                    default: dst = g_W; break; }
    dst[bh * 4096 + e] = s;
}

__global__ void k_rowdotA() {
    int row = blockIdx.x * 8 + (threadIdx.x >> 5);
    int lane = threadIdx.x & 31;
    int bh = row >> 6, j = row & 63;
    const float* Hr = g_H  + bh * 4096 + j * 64;
    const float* Gr = g_G  + bh * 4096 + j * 64;
    const float* Pr = g_P  + bh * 4096 + j * 64;
    const float* Kr = g_RK + bh * 4096 + j * 64;
    float s = Hr[lane] * Gr[lane] + Hr[lane + 32] * Gr[lane + 32]
            - Pr[lane] * Kr[lane] - Pr[lane + 32] * Kr[lane + 32];
    #pragma unroll
    for (int o = 16; o > 0; o >>= 1) s += __shfl_xor_sync(0xffffffffu, s, o);
    if (lane == 0) g_rowdot[row] = 2.0f * s;
}

// GEMM-style updateL: dL = [lsq | q'] @ [G ; -RK^T], fused PGD + renorm.
// grid(BH, 16) x 128. Thread: ty=tid>>3 (16 row-groups of 8), tx=tid&7 (8 col-groups of 8).
__global__ void k_updateL2(const float* __restrict__ q) {
    __shared__ __align__(16) float AT[32 * 132];   // [kk][i]  (A transposed)
    __shared__ __align__(16) float Bs[32 * 68];    // [kk][r]
    int bh = blockIdx.x, i0 = blockIdx.y * 128;
    int tid = threadIdx.x;
    int ty = tid >> 3, tx = tid & 7;
    const float* lsb = g_ls + (size_t)bh * S * RNK + (size_t)i0 * RNK;
    const float* qb  = q + (size_t)bh * S * D + (size_t)i0 * D;
    const float* Gb  = g_G  + bh * 4096;
    const float* RKb = g_RK + bh * 4096;

    float acc[8][8];
    #pragma unroll
    for (int a = 0; a < 8; a++)
        #pragma unroll
        for (int b = 0; b < 8; b++) acc[a][b] = 0.f;

    #pragma unroll
    for (int c = 0; c < 4; c++) {
        int kb = (c & 1) * 32;
        // A fill: AT[kk][i] ; first half lsq (square on fill), second half q/8
        #pragma unroll
        for (int p = 0; p < 32; p++) {
            int e = p * 128 + tid;
            int i = e >> 5, kk = e & 31;
            float x;
            if (c < 2) { x = lsb[i * RNK + kb + kk]; x = x * x; }
            else       { x = 0.125f * qb[i * D + kb + kk]; }
            AT[kk * 132 + i] = x;
        }
        // B fill: Bs[kk][r] ; first half G rows, second half -RK^T (transpose)
        #pragma unroll
        for (int p = 0; p < 16; p++) {
            int e = p * 128 + tid;
            int r0 = e >> 6, cc = e & 63;
            if (c < 2) Bs[r0 * 68 + cc] = Gb[(kb + r0) * 64 + cc];
            else       Bs[((e & 31)) * 68 + (e >> 5)] = -RKb[(e >> 5) * 64 + kb + (e & 31)];
        }
        __syncthreads();
        #pragma unroll 4
        for (int kk = 0; kk < 32; kk++) {
            float4 a0 = *reinterpret_cast<const float4*>(&AT[kk * 132 + ty * 8]);
            float4 a1 = *reinterpret_cast<const float4*>(&AT[kk * 132 + ty * 8 + 4]);
            float4 b0 = *reinterpret_cast<const float4*>(&Bs[kk * 68 + tx * 8]);
            float4 b1 = *reinterpret_cast<const float4*>(&Bs[kk * 68 + tx * 8 + 4]);
            float av[8] = {a0.x,a0.y,a0.z,a0.w,a1.x,a1.y,a1.z,a1.w};
            float bv[8] = {b0.x,b0.y,b0.z,b0.w,b1.x,b1.y,b1.z,b1.w};
            #pragma unroll
            for (int a = 0; a < 8; a++)
                #pragma unroll
                for (int b = 0; b < 8; b++) acc[a][b] += av[a] * bv[b];
        }
        __syncthreads();
    }

    // epilogue: per row i = i0+ty*8+a, this thread owns cols tx*8..tx*8+7
    #pragma unroll
    for (int a = 0; a < 8; a++) {
        int i = i0 + ty * 8 + a;
        float* lsrow = g_ls + ((size_t)bh * S + i) * RNK + tx * 8;
        float4 l0 = *reinterpret_cast<const float4*>(lsrow);
        float4 l1 = *reinterpret_cast<const float4*>(lsrow + 4);
        float ls[8] = {l0.x,l0.y,l0.z,l0.w,l1.x,l1.y,l1.z,l1.w};
        float dl[8];
        float cpart = 0.f;
        #pragma unroll
        for (int b = 0; b < 8; b++) {
            dl[b] = acc[a][b] * 2.0f * ls[b];
            cpart += ls[b] * dl[b];
        }
        #pragma unroll
        for (int o = 1; o < 8; o <<= 1) cpart += __shfl_xor_sync(0xffffffffu, cpart, o);
        float inv = g_invL[bh * S + i];
        float norm_old = (inv > 0.f) ? (1.0f / inv) : 0.0f;
        float nv[8]; float ss = 0.f;
        #pragma unroll
        for (int b = 0; b < 8; b++) {
            float p0 = (inv > 0.f) ? ls[b] * norm_old : ls[b];
            nv[b] = p0 - inv * (dl[b] - ls[b] * cpart);
            ss += nv[b] * nv[b];
        }
        #pragma unroll
        for (int o = 1; o < 8; o <<= 1) ss += __shfl_xor_sync(0xffffffffu, ss, o);
        float nn = sqrtf(ss);
        float rinv = (nn > 0.f) ? (1.0f / nn) : 0.0f;
        #pragma unroll
        for (int b = 0; b < 8; b++) nv[b] = (nn > 0.f) ? nv[b] * rinv : nv[b];
        *reinterpret_cast<float4*>(lsrow)     = make_float4(nv[0], nv[1], nv[2], nv[3]);
        *reinterpret_cast<float4*>(lsrow + 4) = make_float4(nv[4], nv[5], nv[6], nv[7]);
        if (tx == 0) g_invL[bh * S + i] = rinv;
    }
}

// GEMM-style updateR: dtmp^T = [rsq^T | k] @ [H ; -P^T], fused projection + PGD.
// grid(BH, 16) x 128. Output tile rows = t (128), cols = j (64).
__global__ void k_updateR2(const float* __restrict__ kin) {
    __shared__ __align__(16) float AT[32 * 132];   // [kk][t]
    __shared__ __align__(16) float Bs[32 * 68];    // [kk][j]
    __shared__ float sInv[64], sRd[64], sNorm[64];
    int bh = blockIdx.x, t0 = blockIdx.y * 128;
    int tid = threadIdx.x;
    int ty = tid >> 3, tx = tid & 7;
    const float* rsb = g_rs + (size_t)bh * RNK * S;
    const float* kb_ = kin + (size_t)bh * S * D + (size_t)t0 * D;
    const float* Hb  = g_H + bh * 4096;
    const float* Pb  = g_P + bh * 4096;

    if (tid < 64) {
        float iv = g_invR[bh * 64 + tid];
        sInv[tid] = iv;
        sRd [tid] = g_rowdot[bh * 64 + tid];
        sNorm[tid] = (iv > 0.f) ? (1.0f / iv) : 0.0f;
    }

    float acc[8][8];
    #pragma unroll
    for (int a = 0; a < 8; a++)
        #pragma unroll
        for (int b = 0; b < 8; b++) acc[a][b] = 0.f;

    #pragma unroll
    for (int c = 0; c < 4; c++) {
        int kb = (c & 1) * 32;
        if (c < 2) {
            // AT[m][t] = rs[m][t0+t]^2 : contiguous, conflict-free
            #pragma unroll
            for (int p = 0; p < 32; p++) {
                int m = p, t = tid;
                float x = rsb[(kb + m) * S + t0 + t];
                AT[m * 132 + t] = x * x;
            }
            #pragma unroll
            for (int p = 0; p < 16; p++) {
                int e = p * 128 + tid;
                int r0 = e >> 6, cc = e & 63;
                Bs[r0 * 68 + cc] = Hb[(kb + r0) * 64 + cc];
            }
        } else {
            // AT[d][t] = k[t0+t][kb+d] (transpose fill)
            #pragma unroll
            for (int p = 0; p < 32; p++) {
                int e = p * 128 + tid;
                int t = e >> 5, d = e & 31;
                AT[d * 132 + t] = kb_[t * D + kb + d];
            }
            // Bs[d][j] = -P[j][kb+d] (transpose fill)
            #pragma unroll
            for (int p = 0; p < 16; p++) {
                int e = p * 128 + tid;
                int j = e >> 5, d = e & 31;
                Bs[d * 68 + j] = -Pb[j * 64 + kb + d];
            }
        }
        __syncthreads();
        #pragma unroll 4
        for (int kk = 0; kk < 32; kk++) {
            float4 a0 = *reinterpret_cast<const float4*>(&AT[kk * 132 + ty * 8]);
            float4 a1 = *reinterpret_cast<const float4*>(&AT[kk * 132 + ty * 8 + 4]);
            float4 b0 = *reinterpret_cast<const float4*>(&Bs[kk * 68 + tx * 8]);
            float4 b1 = *reinterpret_cast<const float4*>(&Bs[kk * 68 + tx * 8 + 4]);
            float av[8] = {a0.x,a0.y,a0.z,a0.w,a1.x,a1.y,a1.z,a1.w};
            float bv[8] = {b0.x,b0.y,b0.z,b0.w,b1.x,b1.y,b1.z,b1.w};
            #pragma unroll
            for (int a = 0; a < 8; a++)
                #pragma unroll
                for (int b = 0; b < 8; b++) acc[a][b] += av[a] * bv[b];
        }
        __syncthreads();
    }

    // epilogue: thread owns t = t0+ty*8+a, j = tx*8+b. Per j-column: rs, inv, rd.
    #pragma unroll
    for (int b = 0; b < 8; b++) {
        int j = tx * 8 + b;
        float inv = sInv[j], rd = sRd[j], nold = sNorm[j];
        const float* rsrow = rsb + (size_t)j * S + t0 + ty * 8;
        float* rprow = g_Rp + (size_t)bh * RNK * S + (size_t)j * S + t0 + ty * 8;
        float4 r0 = *reinterpret_cast<const float4*>(rsrow);
        float4 r1 = *reinterpret_cast<const float4*>(rsrow + 4);
        float rs[8] = {r0.x,r0.y,r0.z,r0.w,r1.x,r1.y,r1.z,r1.w};
        float nv[8];
        #pragma unroll
        for (int a = 0; a < 8; a++) {
            float dt = acc[a][b] * 2.0f * rs[a];
            float pp = (inv > 0.f) ? rs[a] * nold : rs[a];
            nv[a] = pp - inv * (dt - rs[a] * rd);
        }
        *reinterpret_cast<float4*>(rprow)     = make_float4(nv[0], nv[1], nv[2], nv[3]);
        *reinterpret_cast<float4*>(rprow + 4) = make_float4(nv[4], nv[5], nv[6], nv[7]);
    }
}

// out = lsq^2 @ W. grid(64,16) x 256
__global__ void k_out(float* __restrict__ out) {
    __shared__ float Ws[64 * 65];
    int bh = blockIdx.x;
    for (int e = threadIdx.x; e < 4096; e += 256)
        Ws[(e >> 6) * 65 + (e & 63)] = g_W[bh * 4096 + e];
    __syncthreads();
    int w = threadIdx.x >> 5, lane = threadIdx.x & 31;
    for (int g = 0; g < 4; g++) {
        int i0 = blockIdx.y * 128 + w * 16 + g * 4;
        float lq0[4], lq1[4], o0[4], o1[4];
        #pragma unroll
        for (int r = 0; r < 4; r++) {
            int base = bh * S * RNK + (i0 + r) * RNK;
            float a = g_ls[base + lane], b = g_ls[base + 32 + lane];
            lq0[r] = a * a; lq1[r] = b * b;
            o0[r] = 0.f; o1[r] = 0.f;
        }
        #pragma unroll 4
        for (int j = 0; j < 64; j++) {
            float x0 = Ws[j * 65 + lane], x1 = Ws[j * 65 + 32 + lane];
            #pragma unroll
            for (int r = 0; r < 4; r++) {
                float lv = (j < 32) ? __shfl_sync(0xffffffffu, lq0[r], j)
                                    : __shfl_sync(0xffffffffu, lq1[r], j - 32);
                o0[r] += lv * x0; o1[r] += lv * x1;
            }
        }
        #pragma unroll
        for (int r = 0; r < 4; r++) {
            int ob = bh * S * D + (i0 + r) * D;
            out[ob + lane]      = o0[r];
            out[ob + 32 + lane] = o1[r];
        }
    }
}

extern "C" void kernel_launch(void* const* d_in, const int* in_sizes, int n_in,
                              void* d_out, int out_size) {
    const float* q = (const float*)d_in[0];
    const float* k = (const float*)d_in[1];
    const float* v = (const float*)d_in[2];
    float* out = (float*)d_out;

    uint32_t k1a, k1b, k2a, k2b;
#if JAX_PARTITIONABLE
    tf2x32(0u, 42u, 0u, 0u, &k1a, &k1b);
    tf2x32(0u, 42u, 0u, 1u, &k2a, &k2b);
#else
    { uint32_t a0, b0, a1, b1;
      tf2x32(0u, 42u, 0u, 2u, &a0, &b0);
      tf2x32(0u, 42u, 1u, 3u, &a1, &b1);
      k1a = a0; k1b = a1; k2a = b0; k2b = b1; }
#endif

    k_initL<<<BH * S / 8, 256>>>(k1a, k1b);
    k_initR<<<NELEM / 4 / 256, 256>>>(k2a, k2b);
    k_prepR<<<dim3(BH, 64), 256>>>();
    for (int step = 0; step < 8; step++) {
        k_gemmF<<<dim3(BH, 2, NSPLIT), 128>>>(q, k, v, 0);    // H|P and G|RK partials
        k_gred<<<4 * BH * 4096 / 256, 256>>>(0);
        k_rowdotA<<<BH * RNK / 8, 256>>>();
        k_updateL2<<<dim3(BH, 16), 128>>>(q);
        k_updateR2<<<dim3(BH, 16), 128>>>(k);
        k_prepR<<<dim3(BH, 64), 256>>>();
    }
    k_gemmF<<<dim3(BH, 1, NSPLIT), 128>>>(q, k, v, 2);        // W partials
    k_gred<<<BH * 4096 / 256, 256>>>(4);
    k_out<<<dim3(BH, 16), 256>>>(out);
}